// round 10
// baseline (speedup 1.0000x reference)
#include <cuda_runtime.h>

// ---------------------------------------------------------------------------
// TContextGGANN_39805756899562  —  FINAL (committed, R9-verified)
//
// Algorithmic result (R1, re-verified through R9, rel_err = 0.0 exactly):
// the reference network has an exact fixed point at zero. All four hidden
// states initialize to zeros; every message is elementwise-gated by a hidden
// state (enc * h == 0); the GRU update (1-z)*h + z*tanh(a@Wox.T + (r*h)@Woh.T)
// maps (a=0, h=0) to exactly 0 (every term multiplies an exact 0.0, no
// rounding enters); this holds across all LOOPS iterations; the final
// attention sees Q=K=V=0, so A@V = 0. The returned (h_e, h_l, h_i, h_m) are
// identically zero for any inputs — the ~2e11 FLOPs of the apparent compute
// graph are dead code. The kernel reduces to a 64 MiB zero-fill of the
// poisoned d_out.
//
// Hardware result (R2-R9): the zero-fill is bounded by the L2 write-
// acceptance ceiling, ~2970 B/cyc (~5.86 TB/s @NAT) = 192 slices x ~16 B/cyc
// — half the 6300 B/cyc load cap, and PATH-INDEPENDENT:
//   STG.128  4096 x 4/thr (guarded) : 11.04-11.46 us  <- this kernel (best)
//   STG.128  4096 x 4/thr (exact)   : 11.39 us (predicates are free)
//   STG.128  8192 x 2/thr           : 11.58 us
//   STG.128  1024 x 16/thr          : 11.74 us
//   TMA bulk stores                 : 13.54 us
//   driver memset node              : ~13.5 us
// ncu L2~50% = the write half of the combined LTS read+write port fully
// saturated (store-only kernels cannot exceed ~50% of the combined counter).
// dur-kernel gap (~1.6 us) is graph-replay overhead, node-type-independent
// (R5). Grid shape, unroll depth, predication, and write path are all flat
// at this floor. 64 MiB / 5.86 TB/s = 11.2 us theoretical kernel floor;
// measured 11.0-11.5 us. dur_us = 12.768 reproduced twice (R7, R9).
// No further optimization exists for this problem on this hardware.
// ---------------------------------------------------------------------------

__global__ void __launch_bounds__(256) tcg_zero4(float4* __restrict__ out, int n4) {
    int t = blockIdx.x * blockDim.x + threadIdx.x;
    int total = gridDim.x * blockDim.x;
    const float4 z = make_float4(0.0f, 0.0f, 0.0f, 0.0f);
    // 4 coalesced STG.128 per thread; fully unrolled, predicated bounds
    // (predicates measured free at issue ~11%).
    #pragma unroll
    for (int k = 0; k < 4; ++k) {
        int i = t + k * total;
        if (i < n4) out[i] = z;
    }
}

__global__ void tcg_zero_tail(float* __restrict__ out, int start, int n) {
    int i = start + blockIdx.x * blockDim.x + threadIdx.x;
    if (i < n) out[i] = 0.0f;
}

extern "C" void kernel_launch(void* const* d_in, const int* in_sizes, int n_in,
                              void* d_out, int out_size) {
    (void)d_in; (void)in_sizes; (void)n_in;

    float* out = (float*)d_out;
    int n  = out_size;            // 16,777,216 fp32 for this problem
    int n4 = n >> 2;              // float4 chunks; d_out is 256B-aligned
    int rem_start = n4 << 2;

    if (n4 > 0) {
        const int threads = 256;
        const int per_thread = 4;
        int blocks = (n4 + threads * per_thread - 1) / (threads * per_thread);
        tcg_zero4<<<blocks, threads>>>((float4*)out, n4);   // 4096 blocks here
    }
    if (rem_start < n) {          // never launched for n % 4 == 0
        int rem = n - rem_start;
        int blocks = (rem + 127) / 128;
        tcg_zero_tail<<<blocks, 128>>>(out, rem_start, n);
    }
}

// round 11
// speedup vs baseline: 1.0201x; 1.0201x over previous
#include <cuda_runtime.h>

// ---------------------------------------------------------------------------
// TContextGGANN_39805756899562  —  FINAL family (R11: block-size probe)
//
// Algorithmic result (R1, re-verified through R10, rel_err = 0.0 exactly):
// the reference network has an exact fixed point at zero. All four hidden
// states initialize to zeros; every message is elementwise-gated by a hidden
// state (enc * h == 0); the GRU update (1-z)*h + z*tanh(a@Wox.T + (r*h)@Woh.T)
// maps (a=0, h=0) to exactly 0; the final attention sees Q=K=V=0. Output is
// identically zero for any inputs — the ~2e11 FLOPs of the apparent compute
// graph are dead code. The kernel reduces to a 64 MiB zero-fill of the
// poisoned d_out.
//
// Hardware result (R2-R10): bounded by the path-independent L2 write-
// acceptance ceiling (~2970 B/cyc = ~5.86 TB/s @NAT; L2 counter ~50% = write
// half of the combined LTS port saturated). Measured floor: kernel
// 11.0-11.5 us, dur 12.77-13.06 us across STG shapes, TMA bulk, and driver
// memset. R11 probes the one unswept axis — threads/block 256 -> 512
// (2048 blocks, 4 STG.128/thread) — predicted neutral; reverting to the
// R9 config if not a measurable win.
// ---------------------------------------------------------------------------

__global__ void __launch_bounds__(512) tcg_zero4_b512(float4* __restrict__ out, int n4) {
    int t = blockIdx.x * blockDim.x + threadIdx.x;
    int total = gridDim.x * blockDim.x;
    const float4 z = make_float4(0.0f, 0.0f, 0.0f, 0.0f);
    // 4 coalesced STG.128 per thread; fully unrolled, predicated bounds.
    #pragma unroll
    for (int k = 0; k < 4; ++k) {
        int i = t + k * total;
        if (i < n4) out[i] = z;
    }
}

__global__ void tcg_zero_tail(float* __restrict__ out, int start, int n) {
    int i = start + blockIdx.x * blockDim.x + threadIdx.x;
    if (i < n) out[i] = 0.0f;
}

extern "C" void kernel_launch(void* const* d_in, const int* in_sizes, int n_in,
                              void* d_out, int out_size) {
    (void)d_in; (void)in_sizes; (void)n_in;

    float* out = (float*)d_out;
    int n  = out_size;            // 16,777,216 fp32 for this problem
    int n4 = n >> 2;              // float4 chunks; d_out is 256B-aligned
    int rem_start = n4 << 2;

    if (n4 > 0) {
        const int threads = 512;
        const int per_thread = 4;
        int blocks = (n4 + threads * per_thread - 1) / (threads * per_thread);
        tcg_zero4_b512<<<blocks, threads>>>((float4*)out, n4);   // 2048 blocks
    }
    if (rem_start < n) {          // never launched for n % 4 == 0
        int rem = n - rem_start;
        int blocks = (rem + 127) / 128;
        tcg_zero_tail<<<blocks, 128>>>(out, rem_start, n);
    }
}